// round 12
// baseline (speedup 1.0000x reference)
#include <cuda_runtime.h>
#include <math.h>
#include <stdint.h>

// Zero-initialized at load; last block resets after finalize -> deterministic replays.
__device__ double       g_sum    = 0.0;
__device__ unsigned int g_cnt    = 0u;
__device__ unsigned int g_wpos   = 0u;
__device__ unsigned int g_arrive = 0u;

#define TILE_ROWS 256
#define TILE_FLOATS (TILE_ROWS * 18)        // 4608 floats
#define TILE_BYTES  (TILE_FLOATS * 4)       // 18432 B
#define NBUF 3
#define SMEM_DYN (NBUF * TILE_BYTES)        // 55296 B
#define MAX_BLOCKS 592                      // 148 SMs * 4 resident blocks

__device__ __forceinline__ float sqrt_approx(float x) {
    float r;
    asm("sqrt.approx.f32 %0, %1;" : "=f"(r) : "f"(x));
    return r;
}
__device__ __forceinline__ uint32_t smem_u32(const void* p) {
    uint32_t a;
    asm("{ .reg .u64 t; cvta.to.shared.u64 t, %1; cvt.u32.u64 %0, t; }"
        : "=r"(a) : "l"(p));
    return a;
}
__device__ __forceinline__ void mbar_init(uint32_t mbar, uint32_t count) {
    asm volatile("mbarrier.init.shared.b64 [%0], %1;" :: "r"(mbar), "r"(count) : "memory");
}
__device__ __forceinline__ void mbar_expect_tx(uint32_t mbar, uint32_t bytes) {
    asm volatile("mbarrier.arrive.expect_tx.shared.b64 _, [%0], %1;"
                 :: "r"(mbar), "r"(bytes) : "memory");
}
__device__ __forceinline__ void bulk_g2s(uint32_t dst, const void* src,
                                         uint32_t bytes, uint32_t mbar) {
    asm volatile("cp.async.bulk.shared::cta.global.mbarrier::complete_tx::bytes "
                 "[%0], [%1], %2, [%3];"
                 :: "r"(dst), "l"(src), "r"(bytes), "r"(mbar) : "memory");
}
__device__ __forceinline__ void mbar_wait(uint32_t mbar, uint32_t parity) {
    uint32_t done;
    asm volatile(
        "{\n\t.reg .pred p;\n\t"
        "mbarrier.try_wait.parity.acquire.cta.shared::cta.b64 p, [%1], %2;\n\t"
        "selp.b32 %0, 1, 0, p;\n\t}"
        : "=r"(done) : "r"(mbar), "r"(parity) : "memory");
    if (!done) {
        asm volatile(
            "{\n\t.reg .pred P1;\n\t"
            "WAIT_LOOP_%=:\n\t"
            "mbarrier.try_wait.parity.acquire.cta.shared::cta.b64 P1, [%0], %1, 0x989680;\n\t"
            "@P1 bra.uni WAIT_DONE_%=;\n\t"
            "bra.uni WAIT_LOOP_%=;\n\t"
            "WAIT_DONE_%=:\n\t}"
            :: "r"(mbar), "r"(parity) : "memory");
    }
}

__device__ __forceinline__ void sbl_row(const float* __restrict__ P,
                                        float4 b0, float4 b1,
                                        float& dist_sum, unsigned int& cnt)
{
    const float vx0 = b0.x, vy0 = b0.y;
    const float vx1 = b0.z, vy1 = b0.w;
    const float vx2 = b1.x, vy2 = b1.y;
    const float vx3 = b1.z, vy3 = b1.w;

    // Fan decomposition: tri1=(0->1,1->2,2->0), tri2=(-{2->0},2->3,3->0)
    #define SBL_EDGE_CONST(AX, AY, BX, BY, EX, NDY, C)                          \
        const float EX  = (BX) - (AX);                                          \
        const float NDY = (AY) - (BY);                                          \
        const float C   = fmaf(-(NDY), (AX), -(EX) * (AY));

    SBL_EDGE_CONST(vx0, vy0, vx1, vy1, ex01, ndy01, c01)
    SBL_EDGE_CONST(vx1, vy1, vx2, vy2, ex12, ndy12, c12)
    SBL_EDGE_CONST(vx2, vy2, vx0, vy0, ex20, ndy20, c20)
    SBL_EDGE_CONST(vx2, vy2, vx3, vy3, ex23, ndy23, c23)
    SBL_EDGE_CONST(vx3, vy3, vx0, vy0, ex30, ndy30, c30)
    #undef SBL_EDGE_CONST

    const float cx = (vx0 + vx2) * 0.5f;
    const float cy = (vy0 + vy2) * 0.5f;

    const float2* __restrict__ P2 = (const float2*)P;

    #pragma unroll
    for (int k = 0; k < 9; k++) {
        const float2 p  = P2[k];
        const float  px = p.x;
        const float  py = p.y;

        const int e01 = __float_as_int(fmaf(ex01, py, fmaf(ndy01, px, c01)));
        const int e12 = __float_as_int(fmaf(ex12, py, fmaf(ndy12, px, c12)));
        const int e20 = __float_as_int(fmaf(ex20, py, fmaf(ndy20, px, c20)));
        const int e23 = __float_as_int(fmaf(ex23, py, fmaf(ndy23, px, c23)));
        const int e30 = __float_as_int(fmaf(ex30, py, fmaf(ndy30, px, c30)));

        const int in1 = ~(e01 ^ e12) & ~(e01 ^ e20);
        const int in2 =  (e20 ^ e23) &  (e20 ^ e30);
        const int ins = in1 ^ in2;              // sign set -> inside

        const float dx  = px - cx;
        const float dyc = py - cy;
        const float d   = sqrt_approx(fmaf(dx, dx, dyc * dyc)); // 0.2 folded out

        dist_sum += (ins >= 0) ? d : 0.0f;
        cnt      += ((unsigned int)(~ins)) >> 31;
    }
}

extern __shared__ __align__(16) float s_dyn[];   // NBUF tiles of pts

__global__ void __launch_bounds__(TILE_ROWS)
sbl_fused_kernel(const float* __restrict__ pts,
                 const float* __restrict__ bbox,
                 const float* __restrict__ w,
                 float* __restrict__ out,
                 int N, int ntiles, int nblocks)
{
    __shared__ __align__(8) uint64_t s_mbar[NBUF];

    const int tid = threadIdx.x;
    const int bid = blockIdx.x;

    const uint32_t sb_base   = smem_u32(&s_dyn[0]);
    const uint32_t mbar_base = smem_u32(&s_mbar[0]);

    if (tid == 0) {
        #pragma unroll
        for (int i = 0; i < NBUF; i++) mbar_init(mbar_base + i * 8, 1u);
    }
    __syncthreads();

    // Stage tile TILE into buffer B (thread 0 only). Tail (<16B) via STS,
    // ordered for consumers by the __syncthreads at each iteration top.
    #define SBL_STAGE(B, TILE)                                                  \
        do {                                                                    \
            const int      _base  = (TILE) * TILE_ROWS;                         \
            const int      _nr    = min(TILE_ROWS, N - _base);                  \
            const uint32_t _bytes = (uint32_t)(_nr * 18) * 4u;                  \
            const uint32_t _b16   = _bytes & ~15u;                              \
            const uint32_t _dst   = sb_base + (uint32_t)(B) * TILE_BYTES;       \
            const char*    _src   = (const char*)(pts + (size_t)_base * 18);    \
            mbar_expect_tx(mbar_base + (B) * 8, _b16);                          \
            bulk_g2s(_dst, _src, _b16, mbar_base + (B) * 8);                    \
            for (uint32_t _o = _b16; _o < _bytes; _o += 4u)                     \
                *(float*)((char*)s_dyn + (uint32_t)(B) * TILE_BYTES + _o) =     \
                    *(const float*)(_src + _o);                                 \
        } while (0)

    // ---- Prologue: stage tiles bid and bid+nblocks (prefetch distance 2) ----
    if (tid == 0) {
        if (bid < ntiles)            SBL_STAGE(0, bid);
        if (bid + nblocks < ntiles)  SBL_STAGE(1, bid + nblocks);
    }

    float        dist_sum = 0.0f;
    unsigned int cnt      = 0u;
    unsigned int wp       = 0u;

    int      b      = 0;       // current buffer
    uint32_t phmask = 0u;      // per-buffer parity bits

    for (int t = bid; t < ntiles; t += nblocks) {
        const int base = t * TILE_ROWS;
        const int nr   = min(TILE_ROWS, N - base);

        // bbox/w loads issued early; latency hides under the mbarrier wait
        float4 b0 = make_float4(0.f,0.f,0.f,0.f);
        float4 b1 = make_float4(0.f,1.f,1.f,0.f);
        float  wv = 0.0f;
        if (tid < nr) {
            const float4* __restrict__ bb = (const float4*)(bbox + (size_t)base * 8);
            b0 = bb[2 * tid];
            b1 = bb[2 * tid + 1];
            wv = w[base + tid];
        }

        // All threads finished the previous iteration's compute; the buffer
        // being restaged below (== previous iteration's buffer + NBUF wrap)
        // is safe to overwrite.
        __syncthreads();

        int b2 = b + 2; if (b2 >= NBUF) b2 -= NBUF;
        const int tn = t + 2 * nblocks;
        if (tid == 0 && tn < ntiles) SBL_STAGE(b2, tn);

        // Wait for current buffer's bulk copy.
        const uint32_t par = (phmask >> b) & 1u;
        mbar_wait(mbar_base + b * 8, par);
        phmask ^= (1u << b);

        if (tid < nr) {
            sbl_row((const float*)((char*)s_dyn + (uint32_t)b * TILE_BYTES) + tid * 18,
                    b0, b1, dist_sum, cnt);
            wp += (wv > 0.0f) ? 1u : 0u;
        }

        if (++b >= NBUF) b = 0;
    }
    #undef SBL_STAGE

    // ---- One epilogue per block (cnt block-sum <= 16384? tiles/block ~7 ->
    //      cnt <= 256*9*7 = 16128 < 65536; wp <= 1792) ----
    unsigned int comb = (cnt << 16) | wp;

    #pragma unroll
    for (int o = 16; o > 0; o >>= 1) {
        dist_sum += __shfl_down_sync(0xffffffffu, dist_sum, o);
        comb     += __shfl_down_sync(0xffffffffu, comb, o);
    }

    __shared__ float        red_s[TILE_ROWS / 32];
    __shared__ unsigned int red_c[TILE_ROWS / 32];
    __shared__ bool         s_is_last;

    const int wid  = tid >> 5;
    const int lane = tid & 31;
    if (lane == 0) { red_s[wid] = dist_sum; red_c[wid] = comb; }
    __syncthreads();

    if (tid < 32) {
        const int nw = TILE_ROWS / 32;
        float        s = (lane < nw) ? red_s[lane] : 0.0f;
        unsigned int c = (lane < nw) ? red_c[lane] : 0u;
        #pragma unroll
        for (int o = 4; o > 0; o >>= 1) {
            s += __shfl_down_sync(0xffffffffu, s, o);
            c += __shfl_down_sync(0xffffffffu, c, o);
        }
        if (lane == 0) {
            atomicAdd(&g_sum,  (double)s);
            atomicAdd(&g_cnt,  c >> 16);
            atomicAdd(&g_wpos, c & 0xFFFFu);
            __threadfence();
            const unsigned int ticket = atomicAdd(&g_arrive, 1u);
            s_is_last = (ticket == (unsigned int)(nblocks - 1));
        }
    }
    __syncthreads();

    if (s_is_last && tid == 0) {
        __threadfence();
        const double       S = atomicAdd(&g_sum, 0.0);
        const unsigned int C = g_cnt;
        const unsigned int V = g_wpos;

        double loss_sb = 0.0;
        if (C > 0u) {
            const unsigned int denom = (C > 1u) ? C : 1u;
            loss_sb = 0.2 * S / (double)denom;
        }
        const double avg_factor = (double)((float)V) + 1e-6;
        out[0] = (float)(loss_sb / avg_factor);

        g_sum    = 0.0;
        g_cnt    = 0u;
        g_wpos   = 0u;
        g_arrive = 0u;
        __threadfence();
    }
}

extern "C" void kernel_launch(void* const* d_in, const int* in_sizes, int n_in,
                              void* d_out, int out_size)
{
    const float* pts  = (const float*)d_in[0];
    const float* bbox = (const float*)d_in[1];
    const float* w    = (const float*)d_in[2];
    float* out        = (float*)d_out;

    const int N      = in_sizes[0] / 18;
    const int ntiles = (N + TILE_ROWS - 1) / TILE_ROWS;
    const int grid   = (ntiles < MAX_BLOCKS) ? ntiles : MAX_BLOCKS;

    static bool attr_set = false;
    if (!attr_set) {
        cudaFuncSetAttribute(sbl_fused_kernel,
                             cudaFuncAttributeMaxDynamicSharedMemorySize, SMEM_DYN);
        attr_set = true;
    }

    sbl_fused_kernel<<<grid, TILE_ROWS, SMEM_DYN>>>(pts, bbox, w, out, N, ntiles, grid);
}

// round 13
// speedup vs baseline: 1.0894x; 1.0894x over previous
#include <cuda_runtime.h>
#include <math.h>
#include <stdint.h>

// Zero-initialized at load; last block resets after finalize -> deterministic replays.
__device__ double       g_sum    = 0.0;
__device__ unsigned int g_cnt    = 0u;
__device__ unsigned int g_wpos   = 0u;
__device__ unsigned int g_arrive = 0u;

#define TILE_ROWS 256
#define TILE_FLOATS (TILE_ROWS * 18)    // 4608 floats = 18432 B
#define MAX_BLOCKS 888                  // 148 SMs * 6 resident blocks (37KB smem each)

__device__ __forceinline__ float sqrt_approx(float x) {
    float r;
    asm("sqrt.approx.f32 %0, %1;" : "=f"(r) : "f"(x));
    return r;
}
__device__ __forceinline__ uint32_t smem_u32(const void* p) {
    uint32_t a;
    asm("{ .reg .u64 t; cvta.to.shared.u64 t, %1; cvt.u32.u64 %0, t; }"
        : "=r"(a) : "l"(p));
    return a;
}
__device__ __forceinline__ void mbar_init(uint32_t mbar, uint32_t count) {
    asm volatile("mbarrier.init.shared.b64 [%0], %1;" :: "r"(mbar), "r"(count) : "memory");
}
__device__ __forceinline__ void mbar_expect_tx(uint32_t mbar, uint32_t bytes) {
    asm volatile("mbarrier.arrive.expect_tx.shared.b64 _, [%0], %1;"
                 :: "r"(mbar), "r"(bytes) : "memory");
}
__device__ __forceinline__ void bulk_g2s(uint32_t dst, const void* src,
                                         uint32_t bytes, uint32_t mbar) {
    asm volatile("cp.async.bulk.shared::cta.global.mbarrier::complete_tx::bytes "
                 "[%0], [%1], %2, [%3];"
                 :: "r"(dst), "l"(src), "r"(bytes), "r"(mbar) : "memory");
}
__device__ __forceinline__ void mbar_wait(uint32_t mbar, uint32_t parity) {
    uint32_t done;
    asm volatile(
        "{\n\t.reg .pred p;\n\t"
        "mbarrier.try_wait.parity.acquire.cta.shared::cta.b64 p, [%1], %2;\n\t"
        "selp.b32 %0, 1, 0, p;\n\t}"
        : "=r"(done) : "r"(mbar), "r"(parity) : "memory");
    if (!done) {
        asm volatile(
            "{\n\t.reg .pred P1;\n\t"
            "WAIT_LOOP_%=:\n\t"
            "mbarrier.try_wait.parity.acquire.cta.shared::cta.b64 P1, [%0], %1, 0x989680;\n\t"
            "@P1 bra.uni WAIT_DONE_%=;\n\t"
            "bra.uni WAIT_LOOP_%=;\n\t"
            "WAIT_DONE_%=:\n\t}"
            :: "r"(mbar), "r"(parity) : "memory");
    }
}

__device__ __forceinline__ void sbl_row(const float* __restrict__ P,
                                        float4 b0, float4 b1,
                                        float& dist_sum, unsigned int& cnt)
{
    const float vx0 = b0.x, vy0 = b0.y;
    const float vx1 = b0.z, vy1 = b0.w;
    const float vx2 = b1.x, vy2 = b1.y;
    const float vx3 = b1.z, vy3 = b1.w;

    // Fan decomposition: tri1=(0->1,1->2,2->0), tri2=(-{2->0},2->3,3->0)
    #define SBL_EDGE_CONST(AX, AY, BX, BY, EX, NDY, C)                          \
        const float EX  = (BX) - (AX);                                          \
        const float NDY = (AY) - (BY);                                          \
        const float C   = fmaf(-(NDY), (AX), -(EX) * (AY));

    SBL_EDGE_CONST(vx0, vy0, vx1, vy1, ex01, ndy01, c01)
    SBL_EDGE_CONST(vx1, vy1, vx2, vy2, ex12, ndy12, c12)
    SBL_EDGE_CONST(vx2, vy2, vx0, vy0, ex20, ndy20, c20)
    SBL_EDGE_CONST(vx2, vy2, vx3, vy3, ex23, ndy23, c23)
    SBL_EDGE_CONST(vx3, vy3, vx0, vy0, ex30, ndy30, c30)
    #undef SBL_EDGE_CONST

    const float cx = (vx0 + vx2) * 0.5f;
    const float cy = (vy0 + vy2) * 0.5f;

    const float2* __restrict__ P2 = (const float2*)P;

    #pragma unroll
    for (int k = 0; k < 9; k++) {
        const float2 p  = P2[k];
        const float  px = p.x;
        const float  py = p.y;

        const int e01 = __float_as_int(fmaf(ex01, py, fmaf(ndy01, px, c01)));
        const int e12 = __float_as_int(fmaf(ex12, py, fmaf(ndy12, px, c12)));
        const int e20 = __float_as_int(fmaf(ex20, py, fmaf(ndy20, px, c20)));
        const int e23 = __float_as_int(fmaf(ex23, py, fmaf(ndy23, px, c23)));
        const int e30 = __float_as_int(fmaf(ex30, py, fmaf(ndy30, px, c30)));

        const int in1 = ~(e01 ^ e12) & ~(e01 ^ e20);
        const int in2 =  (e20 ^ e23) &  (e20 ^ e30);
        const int ins = in1 ^ in2;              // sign set -> inside

        const float dx  = px - cx;
        const float dyc = py - cy;
        const float d   = sqrt_approx(fmaf(dx, dx, dyc * dyc)); // 0.2 folded out

        dist_sum += (ins >= 0) ? d : 0.0f;
        cnt      += ((unsigned int)(~ins)) >> 31;
    }
}

__global__ void __launch_bounds__(TILE_ROWS)
sbl_fused_kernel(const float* __restrict__ pts,
                 const float* __restrict__ bbox,
                 const float* __restrict__ w,
                 float* __restrict__ out,
                 int N, int ntiles, int nblocks)
{
    __shared__ __align__(16) float    s_pts[2][TILE_FLOATS];
    __shared__ __align__(8)  uint64_t s_mbar[2];

    const int tid = threadIdx.x;
    const int bid = blockIdx.x;

    const uint32_t mbar0 = smem_u32(&s_mbar[0]);
    const uint32_t mbar1 = smem_u32(&s_mbar[1]);
    const uint32_t sb0   = smem_u32(&s_pts[0][0]);
    const uint32_t sb1   = smem_u32(&s_pts[1][0]);

    if (tid == 0) {
        mbar_init(mbar0, 1u);
        mbar_init(mbar1, 1u);
    }
    __syncthreads();

    // ---- Stage one tile with a single bulk copy (thread 0). Tail bytes
    // (size not multiple of 16) are copied with plain stores; they are
    // ordered for consumers by the __syncthreads preceding each compute.
    #define SBL_STAGE(SBASE, MBAR, TILE)                                        \
        do {                                                                    \
            const int      _base  = (TILE) * TILE_ROWS;                         \
            const int      _nr    = min(TILE_ROWS, N - _base);                  \
            const uint32_t _bytes = (uint32_t)(_nr * 18) * 4u;                  \
            const uint32_t _b16   = _bytes & ~15u;                              \
            const char*    _src   = (const char*)(pts + (size_t)_base * 18);    \
            mbar_expect_tx((MBAR), _b16);                                       \
            bulk_g2s((SBASE), _src, _b16, (MBAR));                              \
            for (uint32_t _o = _b16; _o < _bytes; _o += 4u)                     \
                *(float*)((char*)s_pts + ((SBASE) - sb0) + _o) =                \
                    *(const float*)(_src + _o);                                 \
        } while (0)

    // ---- Prologue: stage first tile into buffer 0 ----
    if (tid == 0 && bid < ntiles) SBL_STAGE(sb0, mbar0, bid);

    float        dist_sum = 0.0f;
    unsigned int cnt      = 0u;
    unsigned int wp       = 0u;

    int      buf = 0;
    uint32_t ph0 = 0u, ph1 = 0u;

    for (int t = bid; t < ntiles; t += nblocks, buf ^= 1) {
        const int base = t * TILE_ROWS;
        const int nr   = min(TILE_ROWS, N - base);

        // bbox/w loads issued early; latency hides under the mbarrier wait
        float4 b0 = make_float4(0.f,0.f,0.f,0.f);
        float4 b1 = make_float4(0.f,1.f,1.f,0.f);
        float  wv = 0.0f;
        if (tid < nr) {
            const float4* __restrict__ bb = (const float4*)(bbox + (size_t)base * 8);
            b0 = bb[2 * tid];
            b1 = bb[2 * tid + 1];
            wv = w[base + tid];
        }

        // All threads done reading the other buffer from the previous iter.
        __syncthreads();

        const int tn = t + nblocks;
        if (tid == 0 && tn < ntiles) {
            if (buf == 0) SBL_STAGE(sb1, mbar1, tn);
            else          SBL_STAGE(sb0, mbar0, tn);
        }

        // Wait for the current buffer's bulk copy.
        if (buf == 0) { mbar_wait(mbar0, ph0); ph0 ^= 1u; }
        else          { mbar_wait(mbar1, ph1); ph1 ^= 1u; }

        if (tid < nr) {
            sbl_row(&s_pts[buf][tid * 18], b0, b1, dist_sum, cnt);
            wp += (wv > 0.0f) ? 1u : 0u;
        }
    }
    #undef SBL_STAGE

    // ---- One epilogue per block (cnt block-sum <= 256*9*5=11520, wp <= 1280) ----
    unsigned int comb = (cnt << 16) | wp;

    #pragma unroll
    for (int o = 16; o > 0; o >>= 1) {
        dist_sum += __shfl_down_sync(0xffffffffu, dist_sum, o);
        comb     += __shfl_down_sync(0xffffffffu, comb, o);
    }

    __shared__ float        red_s[TILE_ROWS / 32];
    __shared__ unsigned int red_c[TILE_ROWS / 32];
    __shared__ bool         s_is_last;

    const int wid  = tid >> 5;
    const int lane = tid & 31;
    if (lane == 0) { red_s[wid] = dist_sum; red_c[wid] = comb; }
    __syncthreads();

    if (tid < 32) {
        const int nw = TILE_ROWS / 32;
        float        s = (lane < nw) ? red_s[lane] : 0.0f;
        unsigned int c = (lane < nw) ? red_c[lane] : 0u;
        #pragma unroll
        for (int o = 4; o > 0; o >>= 1) {
            s += __shfl_down_sync(0xffffffffu, s, o);
            c += __shfl_down_sync(0xffffffffu, c, o);
        }
        if (lane == 0) {
            atomicAdd(&g_sum,  (double)s);
            atomicAdd(&g_cnt,  c >> 16);
            atomicAdd(&g_wpos, c & 0xFFFFu);
            __threadfence();
            const unsigned int ticket = atomicAdd(&g_arrive, 1u);
            s_is_last = (ticket == (unsigned int)(nblocks - 1));
        }
    }
    __syncthreads();

    if (s_is_last && tid == 0) {
        __threadfence();
        const double       S = atomicAdd(&g_sum, 0.0);
        const unsigned int C = g_cnt;
        const unsigned int V = g_wpos;

        double loss_sb = 0.0;
        if (C > 0u) {
            const unsigned int denom = (C > 1u) ? C : 1u;
            loss_sb = 0.2 * S / (double)denom;
        }
        const double avg_factor = (double)((float)V) + 1e-6;
        out[0] = (float)(loss_sb / avg_factor);

        g_sum    = 0.0;
        g_cnt    = 0u;
        g_wpos   = 0u;
        g_arrive = 0u;
        __threadfence();
    }
}

extern "C" void kernel_launch(void* const* d_in, const int* in_sizes, int n_in,
                              void* d_out, int out_size)
{
    const float* pts  = (const float*)d_in[0];
    const float* bbox = (const float*)d_in[1];
    const float* w    = (const float*)d_in[2];
    float* out        = (float*)d_out;

    const int N      = in_sizes[0] / 18;
    const int ntiles = (N + TILE_ROWS - 1) / TILE_ROWS;
    const int grid   = (ntiles < MAX_BLOCKS) ? ntiles : MAX_BLOCKS;

    sbl_fused_kernel<<<grid, TILE_ROWS>>>(pts, bbox, w, out, N, ntiles, grid);
}